// round 2
// baseline (speedup 1.0000x reference)
#include <cuda_runtime.h>
#include <cstdint>

#define B_  8
#define T_  4096
#define DI  256
#define DO  256
#define M_TOTAL (B_ * T_)      // 32768

// Scratch: interleaved (a, b) = (1-f, f*x) pairs, [M_TOTAL][DO] float2 = 64 MB
__device__ float g_ab[(size_t)M_TOTAL * DO * 2];

__device__ __forceinline__ uint32_t f2tf32(float x) {
    uint32_t r;
    asm("cvt.rna.tf32.f32 %0, %1;" : "=r"(r) : "f"(x));
    return r;
}

#define KC        32
#define SSTRIDE   36   // 32 + 4 pad: bank = 4*(lane/4)+lane%4 -> conflict-free

#define MMA_TF32(d, a, b0, b1)                                            \
    asm volatile(                                                         \
        "mma.sync.aligned.m16n8k8.row.col.f32.tf32.tf32.f32 "            \
        "{%0,%1,%2,%3}, {%4,%5,%6,%7}, {%8,%9}, {%0,%1,%2,%3};"          \
        : "+f"((d)[0]), "+f"((d)[1]), "+f"((d)[2]), "+f"((d)[3])          \
        : "r"((a)[0]), "r"((a)[1]), "r"((a)[2]), "r"((a)[3]),             \
          "r"(b0), "r"(b1))

// CTA: 256 threads, tile M=128 x O=64, computes BOTH projections.
// Grid: (DO/64, M_TOTAL/128) = (4, 256)
__global__ __launch_bounds__(256) void qrnn_gemm(
    const float* __restrict__ in,    // [M_TOTAL, DI]
    const float* __restrict__ mask,  // [M_TOTAL]
    const float* __restrict__ Wx,    // [DO, DI]
    const float* __restrict__ bx,    // [DO]
    const float* __restrict__ Wf,    // [DO, DI]
    const float* __restrict__ bf)    // [DO]
{
    __shared__ uint32_t sA[128 * SSTRIDE];
    __shared__ uint32_t sW[2][64 * SSTRIDE];

    const int tid   = threadIdx.x;
    const int lane  = tid & 31;
    const int warp  = tid >> 5;
    const int warpM = warp & 3;      // 4 warps along M (32 rows each)
    const int warpN = warp >> 2;     // 2 warps along O (32 cols each)
    const int gid   = lane >> 2;     // 0..7
    const int tig   = lane & 3;      // 0..3

    const int m0 = blockIdx.y * 128;
    const int o0 = blockIdx.x * 64;

    float accx[2][4][4];
    float accf[2][4][4];
#pragma unroll
    for (int mf = 0; mf < 2; mf++)
#pragma unroll
        for (int nf = 0; nf < 4; nf++)
#pragma unroll
            for (int c = 0; c < 4; c++) { accx[mf][nf][c] = 0.f; accf[mf][nf][c] = 0.f; }

    for (int kc = 0; kc < DI; kc += KC) {
        // Stage A tile: 128 rows x 32 cols (1024 float4, 4 per thread)
#pragma unroll
        for (int i = 0; i < 4; i++) {
            int lin = tid + i * 256;
            int r   = lin >> 3;
            int c4  = (lin & 7) << 2;
            float4 v = *(const float4*)(in + (size_t)(m0 + r) * DI + kc + c4);
            uint32_t* dst = &sA[r * SSTRIDE + c4];
            dst[0] = f2tf32(v.x); dst[1] = f2tf32(v.y);
            dst[2] = f2tf32(v.z); dst[3] = f2tf32(v.w);
        }
        // Stage both weight tiles: 2 x (64 rows x 32 cols) (1024 float4, 4 per thread)
#pragma unroll
        for (int i = 0; i < 4; i++) {
            int lin = tid + i * 256;
            int w   = lin >> 9;          // 0: Wx, 1: Wf
            int rem = lin & 511;
            int r   = rem >> 3;
            int c4  = (rem & 7) << 2;
            const float* Wp = w ? Wf : Wx;
            float4 v = *(const float4*)(Wp + (size_t)(o0 + r) * DI + kc + c4);
            uint32_t* dst = &sW[w][r * SSTRIDE + c4];
            dst[0] = f2tf32(v.x); dst[1] = f2tf32(v.y);
            dst[2] = f2tf32(v.z); dst[3] = f2tf32(v.w);
        }
        __syncthreads();

#pragma unroll
        for (int ks = 0; ks < 4; ks++) {
            const int kk = ks * 8;
            uint32_t a[2][4];
#pragma unroll
            for (int mf = 0; mf < 2; mf++) {
                int rbase = (warpM * 32 + mf * 16 + gid) * SSTRIDE + kk + tig;
                a[mf][0] = sA[rbase];
                a[mf][1] = sA[rbase + 8 * SSTRIDE];
                a[mf][2] = sA[rbase + 4];
                a[mf][3] = sA[rbase + 8 * SSTRIDE + 4];
            }
#pragma unroll
            for (int nf = 0; nf < 4; nf++) {
                int ob = (warpN * 32 + nf * 8 + gid) * SSTRIDE + kk + tig;
                uint32_t wx0 = sW[0][ob], wx1 = sW[0][ob + 4];
                uint32_t wf0 = sW[1][ob], wf1 = sW[1][ob + 4];
#pragma unroll
                for (int mf = 0; mf < 2; mf++) {
                    MMA_TF32(accx[mf][nf], a[mf], wx0, wx1);
                    MMA_TF32(accf[mf][nf], a[mf], wf0, wf1);
                }
            }
        }
        __syncthreads();
    }

    // Epilogue: x = tanh(zx + bx), f = sigmoid(zf + bf + mask*1e4)
    // store (a,b) = (1-f, f*x) interleaved; pack 2 adjacent cols -> float4 STG.128
#pragma unroll
    for (int mf = 0; mf < 2; mf++) {
#pragma unroll
        for (int rr = 0; rr < 2; rr++) {
            int m = m0 + warpM * 32 + mf * 16 + rr * 8 + gid;
            float mk = mask[m] * 10000.0f;
#pragma unroll
            for (int nf = 0; nf < 4; nf++) {
                int o = o0 + warpN * 32 + nf * 8 + 2 * tig;
                float zx0 = accx[mf][nf][rr * 2 + 0] + bx[o];
                float zx1 = accx[mf][nf][rr * 2 + 1] + bx[o + 1];
                float zf0 = accf[mf][nf][rr * 2 + 0] + bf[o] + mk;
                float zf1 = accf[mf][nf][rr * 2 + 1] + bf[o + 1] + mk;
                float x0 = tanhf(zx0);
                float x1 = tanhf(zx1);
                float f0 = 1.0f / (1.0f + __expf(-zf0));
                float f1 = 1.0f / (1.0f + __expf(-zf1));
                float4 st;
                st.x = 1.0f - f0; st.y = f0 * x0;
                st.z = 1.0f - f1; st.w = f1 * x1;
                *(float4*)(&g_ab[((size_t)m * DO + o) * 2]) = st;
            }
        }
    }
}

// Sequential forget-mult scan: one thread per (b, o) chain.
// 64 CTAs x 32 threads -> 1 warp/SM across 64 SMs (chain-latency + DRAM bound).
__global__ __launch_bounds__(32) void qrnn_scan(float* __restrict__ out)
{
    const int b = blockIdx.x >> 3;
    const int o = ((blockIdx.x & 7) << 5) + threadIdx.x;

    const float2* ab = (const float2*)g_ab + (size_t)b * T_ * DO + o;
    float* op = out + (size_t)b * T_ * DO + o;

    float h = 0.0f;
#pragma unroll 8
    for (int t = 0; t < T_; t++) {
        float2 v = ab[(size_t)t * DO];   // (a, b)
        h = fmaf(v.x, h, v.y);
        op[(size_t)t * DO] = h;
    }
}

extern "C" void kernel_launch(void* const* d_in, const int* in_sizes, int n_in,
                              void* d_out, int out_size)
{
    const float* in   = (const float*)d_in[0];
    const float* mask = (const float*)d_in[1];
    const float* Wx   = (const float*)d_in[2];
    const float* bx   = (const float*)d_in[3];
    const float* Wf   = (const float*)d_in[4];
    const float* bf   = (const float*)d_in[5];
    float* out = (float*)d_out;

    dim3 grid(DO / 64, M_TOTAL / 128);   // (4, 256)
    qrnn_gemm<<<grid, 256>>>(in, mask, Wx, bx, Wf, bf);
    qrnn_scan<<<64, 32>>>(out);
}

// round 3
// speedup vs baseline: 3.1521x; 3.1521x over previous
#include <cuda_runtime.h>
#include <cstdint>

#define B_  8
#define T_  4096
#define DI  256
#define DO  256
#define M_TOTAL (B_ * T_)      // 32768

#define NCH   32               // chunks per sequence
#define CHUNK (T_ / NCH)       // 128 steps per chunk

// Scratch: interleaved (a, b) = (1-f, f*x) pairs, [M_TOTAL][DO] float2 = 64 MB
__device__ float g_ab[(size_t)M_TOTAL * DO * 2];
// Per-(b, chunk, o) carry composition and resolved chunk-entry state
__device__ float g_cA[B_ * NCH * DO];
__device__ float g_cS[B_ * NCH * DO];
__device__ float g_hin[B_ * NCH * DO];

__device__ __forceinline__ uint32_t f2tf32(float x) {
    uint32_t r;
    asm("cvt.rna.tf32.f32 %0, %1;" : "=r"(r) : "f"(x));
    return r;
}

#define KC        32
#define SSTRIDE   36   // 32 + 4 pad: bank = 4*(lane/4)+lane%4 -> conflict-free

#define MMA_TF32(d, a, b0, b1)                                            \
    asm volatile(                                                         \
        "mma.sync.aligned.m16n8k8.row.col.f32.tf32.tf32.f32 "            \
        "{%0,%1,%2,%3}, {%4,%5,%6,%7}, {%8,%9}, {%0,%1,%2,%3};"          \
        : "+f"((d)[0]), "+f"((d)[1]), "+f"((d)[2]), "+f"((d)[3])          \
        : "r"((a)[0]), "r"((a)[1]), "r"((a)[2]), "r"((a)[3]),             \
          "r"(b0), "r"(b1))

// CTA: 256 threads, tile M=128 x O=64, computes BOTH projections.
// Grid: (DO/64, M_TOTAL/128) = (4, 256)
__global__ __launch_bounds__(256) void qrnn_gemm(
    const float* __restrict__ in,    // [M_TOTAL, DI]
    const float* __restrict__ mask,  // [M_TOTAL]
    const float* __restrict__ Wx,    // [DO, DI]
    const float* __restrict__ bx,    // [DO]
    const float* __restrict__ Wf,    // [DO, DI]
    const float* __restrict__ bf)    // [DO]
{
    __shared__ uint32_t sA[128 * SSTRIDE];
    __shared__ uint32_t sW[2][64 * SSTRIDE];

    const int tid   = threadIdx.x;
    const int lane  = tid & 31;
    const int warp  = tid >> 5;
    const int warpM = warp & 3;      // 4 warps along M (32 rows each)
    const int warpN = warp >> 2;     // 2 warps along O (32 cols each)
    const int gid   = lane >> 2;     // 0..7
    const int tig   = lane & 3;      // 0..3

    const int m0 = blockIdx.y * 128;
    const int o0 = blockIdx.x * 64;

    float accx[2][4][4];
    float accf[2][4][4];
#pragma unroll
    for (int mf = 0; mf < 2; mf++)
#pragma unroll
        for (int nf = 0; nf < 4; nf++)
#pragma unroll
            for (int c = 0; c < 4; c++) { accx[mf][nf][c] = 0.f; accf[mf][nf][c] = 0.f; }

    for (int kc = 0; kc < DI; kc += KC) {
        // Stage A tile: 128 rows x 32 cols (1024 float4, 4 per thread)
#pragma unroll
        for (int i = 0; i < 4; i++) {
            int lin = tid + i * 256;
            int r   = lin >> 3;
            int c4  = (lin & 7) << 2;
            float4 v = *(const float4*)(in + (size_t)(m0 + r) * DI + kc + c4);
            uint32_t* dst = &sA[r * SSTRIDE + c4];
            dst[0] = f2tf32(v.x); dst[1] = f2tf32(v.y);
            dst[2] = f2tf32(v.z); dst[3] = f2tf32(v.w);
        }
        // Stage both weight tiles: 2 x (64 rows x 32 cols) (1024 float4, 4 per thread)
#pragma unroll
        for (int i = 0; i < 4; i++) {
            int lin = tid + i * 256;
            int w   = lin >> 9;          // 0: Wx, 1: Wf
            int rem = lin & 511;
            int r   = rem >> 3;
            int c4  = (rem & 7) << 2;
            const float* Wp = w ? Wf : Wx;
            float4 v = *(const float4*)(Wp + (size_t)(o0 + r) * DI + kc + c4);
            uint32_t* dst = &sW[w][r * SSTRIDE + c4];
            dst[0] = f2tf32(v.x); dst[1] = f2tf32(v.y);
            dst[2] = f2tf32(v.z); dst[3] = f2tf32(v.w);
        }
        __syncthreads();

#pragma unroll
        for (int ks = 0; ks < 4; ks++) {
            const int kk = ks * 8;
            uint32_t a[2][4];
#pragma unroll
            for (int mf = 0; mf < 2; mf++) {
                int rbase = (warpM * 32 + mf * 16 + gid) * SSTRIDE + kk + tig;
                a[mf][0] = sA[rbase];
                a[mf][1] = sA[rbase + 8 * SSTRIDE];
                a[mf][2] = sA[rbase + 4];
                a[mf][3] = sA[rbase + 8 * SSTRIDE + 4];
            }
#pragma unroll
            for (int nf = 0; nf < 4; nf++) {
                int ob = (warpN * 32 + nf * 8 + gid) * SSTRIDE + kk + tig;
                uint32_t wx0 = sW[0][ob], wx1 = sW[0][ob + 4];
                uint32_t wf0 = sW[1][ob], wf1 = sW[1][ob + 4];
#pragma unroll
                for (int mf = 0; mf < 2; mf++) {
                    MMA_TF32(accx[mf][nf], a[mf], wx0, wx1);
                    MMA_TF32(accf[mf][nf], a[mf], wf0, wf1);
                }
            }
        }
        __syncthreads();
    }

    // Epilogue: x = tanh(zx + bx), f = sigmoid(zf + bf + mask*1e4)
    // store (a,b) = (1-f, f*x) interleaved; pack 2 adjacent cols -> float4 STG.128
#pragma unroll
    for (int mf = 0; mf < 2; mf++) {
#pragma unroll
        for (int rr = 0; rr < 2; rr++) {
            int m = m0 + warpM * 32 + mf * 16 + rr * 8 + gid;
            float mk = mask[m] * 10000.0f;
#pragma unroll
            for (int nf = 0; nf < 4; nf++) {
                int o = o0 + warpN * 32 + nf * 8 + 2 * tig;
                float zx0 = accx[mf][nf][rr * 2 + 0] + bx[o];
                float zx1 = accx[mf][nf][rr * 2 + 1] + bx[o + 1];
                float zf0 = accf[mf][nf][rr * 2 + 0] + bf[o] + mk;
                float zf1 = accf[mf][nf][rr * 2 + 1] + bf[o + 1] + mk;
                float x0 = tanhf(zx0);
                float x1 = tanhf(zx1);
                float f0 = 1.0f / (1.0f + __expf(-zf0));
                float f1 = 1.0f / (1.0f + __expf(-zf1));
                float4 st;
                st.x = 1.0f - f0; st.y = f0 * x0;
                st.z = 1.0f - f1; st.w = f1 * x1;
                *(float4*)(&g_ab[((size_t)m * DO + o) * 2]) = st;
            }
        }
    }
}

// ---------------- Chunk-parallel linear-recurrence scan ----------------
// Phase 1: per-(b, chunk, o) composition (A = prod a, S = local scan from 0).
// Grid (B_, NCH) x 256 threads -> 2048 warps.
__global__ __launch_bounds__(256) void scan_carry()
{
    const int b = blockIdx.x;
    const int c = blockIdx.y;
    const int o = threadIdx.x;

    const float2* __restrict__ ab =
        (const float2*)g_ab + ((size_t)b * T_ + (size_t)c * CHUNK) * DO + o;

    float A = 1.0f, S = 0.0f;
#pragma unroll 8
    for (int t = 0; t < CHUNK; t++) {
        float2 v = ab[(size_t)t * DO];
        S = fmaf(v.x, S, v.y);
        A = A * v.x;
    }
    const int idx = (b * NCH + c) * DO + o;
    g_cA[idx] = A;
    g_cS[idx] = S;
}

// Phase 2: per-chain serial combine over NCH chunk carries (32 steps).
__global__ __launch_bounds__(256) void scan_combine()
{
    const int b = blockIdx.x;
    const int o = threadIdx.x;

    float h = 0.0f;
#pragma unroll
    for (int c = 0; c < NCH; c++) {
        const int idx = (b * NCH + c) * DO + o;
        g_hin[idx] = h;
        h = fmaf(g_cA[idx], h, g_cS[idx]);
    }
}

// Phase 3: re-scan each chunk from its exact entry state, writing output.
__global__ __launch_bounds__(256) void scan_apply(float* __restrict__ out)
{
    const int b = blockIdx.x;
    const int c = blockIdx.y;
    const int o = threadIdx.x;

    const size_t base = ((size_t)b * T_ + (size_t)c * CHUNK) * DO + o;
    const float2* __restrict__ ab = (const float2*)g_ab + base;
    float* __restrict__ op = out + base;

    float h = g_hin[(b * NCH + c) * DO + o];
#pragma unroll 8
    for (int t = 0; t < CHUNK; t++) {
        float2 v = ab[(size_t)t * DO];
        h = fmaf(v.x, h, v.y);
        op[(size_t)t * DO] = h;
    }
}

extern "C" void kernel_launch(void* const* d_in, const int* in_sizes, int n_in,
                              void* d_out, int out_size)
{
    const float* in   = (const float*)d_in[0];
    const float* mask = (const float*)d_in[1];
    const float* Wx   = (const float*)d_in[2];
    const float* bx   = (const float*)d_in[3];
    const float* Wf   = (const float*)d_in[4];
    const float* bf   = (const float*)d_in[5];
    float* out = (float*)d_out;

    dim3 ggrid(DO / 64, M_TOTAL / 128);   // (4, 256)
    qrnn_gemm<<<ggrid, 256>>>(in, mask, Wx, bx, Wf, bf);

    dim3 sgrid(B_, NCH);                  // (8, 32)
    scan_carry<<<sgrid, 256>>>();
    scan_combine<<<B_, 256>>>();
    scan_apply<<<sgrid, 256>>>(out);
}